// round 1
// baseline (speedup 1.0000x reference)
#include <cuda_runtime.h>

#define B_   8192
#define N_   40
#define F_   256
#define NF   10240              // N_ * F_
#define TOT  83886080           // B_ * N_ * F_
#define NPART 64

// scratch (device globals: allocation-free per harness rules)
__device__ float g_A[TOT];                // blockdiag(adj) @ input
__device__ float g_psum[NPART * NF];
__device__ float g_psumsq[NPART * NF];
__device__ float g_scale[NF];
__device__ float g_shift[NF];

// ---------------------------------------------------------------------------
// K1: A'[b, s+r, f] = sum_c adj[b, s+r, s+c] * input[b, s+c, f]
// grid (4, B_), 256 threads (one per f)
// ---------------------------------------------------------------------------
__global__ void k1_blockdiag(const float* __restrict__ input,
                             const float* __restrict__ adj) {
    const int b = blockIdx.y;
    const int s = blockIdx.x * 10;
    const int f = threadIdx.x;

    __shared__ float sadj[10][10];
    if (f < 100) {
        int r = f / 10, c = f % 10;
        sadj[r][c] = adj[((size_t)b * 40 + s + r) * 40 + s + c];
    }
    __syncthreads();

    const float* ip = input + ((size_t)b * 40 + s) * 256 + f;
    float x[10];
#pragma unroll
    for (int c = 0; c < 10; ++c) x[c] = ip[c * 256];

    float* op = g_A + ((size_t)b * 40 + s) * 256 + f;
#pragma unroll
    for (int r = 0; r < 10; ++r) {
        float acc = 0.f;
#pragma unroll
        for (int c = 0; c < 10; ++c) acc = fmaf(sadj[r][c], x[c], acc);
        op[r * 256] = acc;
    }
}

// ---------------------------------------------------------------------------
// K2: Y = g_A[327680 x 256] @ W[256 x 256]  (row-major), FFMA SGEMM
// 128x128 tile / CTA, 256 threads, 8x8 per thread, BK=8 double-buffered
// ---------------------------------------------------------------------------
__global__ __launch_bounds__(256, 2)
void k2_gemm(const float* __restrict__ Bmat, float* __restrict__ Y) {
    __shared__ float As[2][8][128];
    __shared__ float Bs[2][8][128];

    const int tid = threadIdx.x;
    const int tx = tid & 15;         // 0..15  -> col group
    const int ty = tid >> 4;         // 0..15  -> row group
    const int rowBase = blockIdx.x * 128;
    const int colBase = blockIdx.y * 128;

    const int aRow = tid >> 1;        // 0..127
    const int aCol = (tid & 1) * 4;   // 0 or 4
    const int bRow = tid >> 5;        // 0..7
    const int bCol = (tid & 31) * 4;  // 0..124

    const float* Ag = g_A + (size_t)(rowBase + aRow) * 256 + aCol;
    const float* Bg = Bmat + (size_t)bRow * 256 + colBase + bCol;

    float acc[8][8];
#pragma unroll
    for (int i = 0; i < 8; ++i)
#pragma unroll
        for (int j = 0; j < 8; ++j) acc[i][j] = 0.f;

    // prologue: stage 0
    {
        float4 a = *(const float4*)Ag;
        As[0][aCol + 0][aRow] = a.x;
        As[0][aCol + 1][aRow] = a.y;
        As[0][aCol + 2][aRow] = a.z;
        As[0][aCol + 3][aRow] = a.w;
        *(float4*)&Bs[0][bRow][bCol] = *(const float4*)Bg;
    }
    __syncthreads();

#pragma unroll 1
    for (int kt = 0; kt < 32; ++kt) {
        const int cur = kt & 1;
        if (kt < 31) {
            float4 a = *(const float4*)(Ag + (kt + 1) * 8);
            float4 b = *(const float4*)(Bg + (size_t)(kt + 1) * 8 * 256);
            const int nxt = cur ^ 1;
            As[nxt][aCol + 0][aRow] = a.x;
            As[nxt][aCol + 1][aRow] = a.y;
            As[nxt][aCol + 2][aRow] = a.z;
            As[nxt][aCol + 3][aRow] = a.w;
            *(float4*)&Bs[nxt][bRow][bCol] = b;
        }
#pragma unroll
        for (int k = 0; k < 8; ++k) {
            float ra[8], rb[8];
            *(float4*)(ra)     = *(const float4*)&As[cur][k][ty * 8];
            *(float4*)(ra + 4) = *(const float4*)&As[cur][k][ty * 8 + 4];
            *(float4*)(rb)     = *(const float4*)&Bs[cur][k][tx * 8];
            *(float4*)(rb + 4) = *(const float4*)&Bs[cur][k][tx * 8 + 4];
#pragma unroll
            for (int i = 0; i < 8; ++i)
#pragma unroll
                for (int j = 0; j < 8; ++j)
                    acc[i][j] = fmaf(ra[i], rb[j], acc[i][j]);
        }
        __syncthreads();
    }

    float* Cp = Y + (size_t)(rowBase + ty * 8) * 256 + colBase + tx * 8;
#pragma unroll
    for (int i = 0; i < 8; ++i) {
        *(float4*)(Cp + (size_t)i * 256)     = make_float4(acc[i][0], acc[i][1], acc[i][2], acc[i][3]);
        *(float4*)(Cp + (size_t)i * 256 + 4) = make_float4(acc[i][4], acc[i][5], acc[i][6], acc[i][7]);
    }
}

// ---------------------------------------------------------------------------
// K3: partial batch sums per feature (n,f). grid (NF/256, NPART), 256 thr.
// Partition p reduces batches [p*128, (p+1)*128). Deterministic (no atomics).
// ---------------------------------------------------------------------------
__global__ void k3_partial(const float* __restrict__ Y) {
    const int nf = blockIdx.x * 256 + threadIdx.x;
    const int p  = blockIdx.y;
    const float* yp = Y + (size_t)p * 128 * NF + nf;
    float s = 0.f, s2 = 0.f;
#pragma unroll 4
    for (int i = 0; i < 128; ++i) {
        float v = yp[(size_t)i * NF];
        s += v;
        s2 = fmaf(v, v, s2);
    }
    g_psum[p * NF + nf]   = s;
    g_psumsq[p * NF + nf] = s2;
}

// ---------------------------------------------------------------------------
// K3b: fold partials -> scale/shift per (n,f). grid NF/256, 256 threads.
// ---------------------------------------------------------------------------
__global__ void k3b_scaleshift(const float* __restrict__ gamma,
                               const float* __restrict__ beta) {
    const int nf = blockIdx.x * 256 + threadIdx.x;
    float s = 0.f, s2 = 0.f;
#pragma unroll 1
    for (int p = 0; p < NPART; ++p) {
        s  += g_psum[p * NF + nf];
        s2 += g_psumsq[p * NF + nf];
    }
    const float inv = 1.f / (float)B_;
    float mean = s * inv;
    float var  = fmaxf(s2 * inv - mean * mean, 0.f);
    int n   = nf >> 8;     // 0..39
    int blk = n / 10;      // 0..3
    float g  = gamma[blk * NF + nf];
    float sc = g * rsqrtf(var + 1e-5f);
    float bsum = beta[nf] + beta[NF + nf] + beta[2 * NF + nf] + beta[3 * NF + nf];
    g_scale[nf] = sc;
    g_shift[nf] = fmaf(-mean, sc, bsum);
}

// ---------------------------------------------------------------------------
// K4: in-place normalize: out = Y * scale[nf] + shift[nf], float4.
// ---------------------------------------------------------------------------
__global__ void k4_normalize(float* __restrict__ Y) {
    const size_t gid = (size_t)blockIdx.x * blockDim.x + threadIdx.x;
    const int nf4 = (int)(gid % (NF / 4));
    float4 y  = ((const float4*)Y)[gid];
    float4 sc = ((const float4*)g_scale)[nf4];
    float4 sh = ((const float4*)g_shift)[nf4];
    y.x = fmaf(y.x, sc.x, sh.x);
    y.y = fmaf(y.y, sc.y, sh.y);
    y.z = fmaf(y.z, sc.z, sh.z);
    y.w = fmaf(y.w, sc.w, sh.w);
    ((float4*)Y)[gid] = y;
}

// ---------------------------------------------------------------------------
extern "C" void kernel_launch(void* const* d_in, const int* in_sizes, int n_in,
                              void* d_out, int out_size) {
    const float* input = (const float*)d_in[0];
    const float* adj   = (const float*)d_in[1];
    const float* W     = (const float*)d_in[2];
    const float* gamma = (const float*)d_in[3];
    const float* beta  = (const float*)d_in[4];
    float* out = (float*)d_out;

    k1_blockdiag<<<dim3(4, B_), 256>>>(input, adj);
    k2_gemm<<<dim3(TOT / F_ / 128, 2), 256>>>(W, out);          // Y -> d_out
    k3_partial<<<dim3(NF / 256, NPART), 256>>>(out);
    k3b_scaleshift<<<NF / 256, 256>>>(gamma, beta);
    k4_normalize<<<(TOT / 4) / 256, 256>>>(out);                // in-place
}

// round 3
// speedup vs baseline: 2.2726x; 2.2726x over previous
#include <cuda_runtime.h>
#include <cuda_bf16.h>
#include <cstdint>

#define B_   8192
#define N_   40
#define F_   256
#define NF   10240
#define TOT  83886080
#define NPART 16

// ---------------- device scratch (no allocation allowed) --------------------
__device__ __nv_bfloat16 g_Ahi[TOT];
__device__ __nv_bfloat16 g_Alo[TOT];
__device__ __nv_bfloat16 g_Whi[F_ * F_];   // K-major: [fout][fin]
__device__ __nv_bfloat16 g_Wlo[F_ * F_];
__device__ float g_psum[NPART * NF];
__device__ float g_psumsq[NPART * NF];
__device__ float g_scale[NF];
__device__ float g_shift[NF];

// ---------------- helpers ---------------------------------------------------
__device__ __forceinline__ uint32_t smem_u32(const void* p) {
    uint32_t a;
    asm("{ .reg .u64 t; cvta.to.shared.u64 t, %1; cvt.u32.u64 %0, t; }" : "=r"(a) : "l"(p));
    return a;
}
__device__ __forceinline__ void cp16(uint32_t dst, const void* src) {
    asm volatile("cp.async.cg.shared.global [%0], [%1], 16;" :: "r"(dst), "l"(src));
}
#define CP_COMMIT() asm volatile("cp.async.commit_group;" ::: "memory")
#define CP_WAIT(n)  asm volatile("cp.async.wait_group %0;" :: "n"(n) : "memory")

#define LDSM4(r, addr)                                                          \
    asm volatile("ldmatrix.sync.aligned.m8n8.x4.shared.b16 {%0,%1,%2,%3}, [%4];"\
        : "=r"((r)[0]), "=r"((r)[1]), "=r"((r)[2]), "=r"((r)[3]) : "r"(addr))

#define MMA(c, a, b)                                                            \
    asm volatile("mma.sync.aligned.m16n8k16.row.col.f32.bf16.bf16.f32 "         \
        "{%0,%1,%2,%3}, {%4,%5,%6,%7}, {%8,%9}, {%0,%1,%2,%3};"                 \
        : "+f"((c)[0]), "+f"((c)[1]), "+f"((c)[2]), "+f"((c)[3])                \
        : "r"((a)[0]), "r"((a)[1]), "r"((a)[2]), "r"((a)[3]),                   \
          "r"((b)[0]), "r"((b)[1]))

// ---------------------------------------------------------------------------
// K0: W [fin=256][fout=256] row-major -> hi/lo bf16, K-major [fout][fin]
// ---------------------------------------------------------------------------
__global__ void k0_wprep(const float* __restrict__ W) {
    int k = blockIdx.x, n = threadIdx.x;
    float v = W[k * 256 + n];
    __nv_bfloat16 h = __float2bfloat16(v);
    g_Whi[n * 256 + k] = h;
    g_Wlo[n * 256 + k] = __float2bfloat16(v - __bfloat162float(h));
}

// ---------------------------------------------------------------------------
// K1: blockdiag bmm -> split bf16.  grid (4, B_), 256 threads (one per fin)
// ---------------------------------------------------------------------------
__global__ void k1_blockdiag(const float* __restrict__ input,
                             const float* __restrict__ adj) {
    const int b = blockIdx.y;
    const int s = blockIdx.x * 10;
    const int f = threadIdx.x;

    __shared__ float sadj[10][10];
    if (f < 100) {
        int r = f / 10, c = f % 10;
        sadj[r][c] = adj[((size_t)b * 40 + s + r) * 40 + s + c];
    }
    __syncthreads();

    const float* ip = input + ((size_t)b * 40 + s) * 256 + f;
    float x[10];
#pragma unroll
    for (int c = 0; c < 10; ++c) x[c] = ip[c * 256];

    const size_t ob = ((size_t)b * 40 + s) * 256 + f;
#pragma unroll
    for (int r = 0; r < 10; ++r) {
        float acc = 0.f;
#pragma unroll
        for (int c = 0; c < 10; ++c) acc = fmaf(sadj[r][c], x[c], acc);
        __nv_bfloat16 h = __float2bfloat16(acc);
        g_Ahi[ob + (size_t)r * 256] = h;
        g_Alo[ob + (size_t)r * 256] = __float2bfloat16(acc - __bfloat162float(h));
    }
}

// ---------------------------------------------------------------------------
// K2: split-bf16 HMMA GEMM.  Y[327680 x 256] = A[.,256] @ Wt[256 x 256]^T
// CTA: 128x128 tile, 8 warps (32x64 each), BK=64, double-buffered cp.async.
// 3 passes into one fp32 accumulator: hi*hi + lo*hi + hi*lo.
// smem layout (xor-swizzled 128B rows):
//   A: buf*32768 + comp*16384 + row*128 + swz16
//   B: 65536 + buf*32768 + comp*16384 + n*128 + swz16
// ---------------------------------------------------------------------------
#define SMEM_K2 131072

__global__ __launch_bounds__(256, 1)
void k2_mma(float* __restrict__ Y) {
    extern __shared__ char smem[];
    const uint32_t sb = smem_u32(smem);
    const int tid = threadIdx.x;
    const int lane = tid & 31;
    const int wid = tid >> 5;
    const int wr = wid >> 1;          // 0..3  row group (x32)
    const int wc = wid & 1;           // 0..1  col group (x64)
    const int rowBase = (blockIdx.x >> 1) * 128;
    const int colBase = (blockIdx.x & 1) * 128;

    const char* aH = (const char*)g_Ahi + (size_t)rowBase * 512;
    const char* aL = (const char*)g_Alo + (size_t)rowBase * 512;
    const char* bH = (const char*)g_Whi + (size_t)colBase * 512;
    const char* bL = (const char*)g_Wlo + (size_t)colBase * 512;

    // chunk loader: 1024 16B-units per tensor-comp, 256 threads -> 4 iters
    auto loadChunk = [&](int kc, int buf) {
        const uint32_t ab = sb + buf * 32768;
        const uint32_t bb = sb + 65536 + buf * 32768;
#pragma unroll
        for (int it = 0; it < 4; ++it) {
            int u = it * 256 + tid;
            int r = u >> 3, o = u & 7;
            size_t g = (size_t)r * 512 + (size_t)kc * 128 + o * 16;
            uint32_t so = r * 128 + ((o ^ (r & 7)) << 4);
            cp16(ab + so,         aH + g);
            cp16(ab + 16384 + so, aL + g);
            cp16(bb + so,         bH + g);
            cp16(bb + 16384 + so, bL + g);
        }
    };

    float acc[2][8][4];
#pragma unroll
    for (int mt = 0; mt < 2; ++mt)
#pragma unroll
        for (int nt = 0; nt < 8; ++nt)
#pragma unroll
            for (int q = 0; q < 4; ++q) acc[mt][nt][q] = 0.f;

    loadChunk(0, 0);
    CP_COMMIT();

    // per-lane fragment address components
    const int aRow0 = wr * 32 + (lane & 15);            // + mt*16
    const int aSwX = lane & 7;                          // (row&7) for A and B
    const int aKU = lane >> 4;                          // k-unit offset 0/1
    const int bN0 = wc * 64 + (lane & 7) + ((lane >> 4) & 1) * 8;  // + p*16
    const int bKU = (lane >> 3) & 1;

    int buf = 0;
#pragma unroll
    for (int kc = 0; kc < 4; ++kc) {
        if (kc < 3) {
            loadChunk(kc + 1, buf ^ 1);
            CP_COMMIT();
            CP_WAIT(1);
        } else {
            CP_WAIT(0);
        }
        __syncthreads();

        const uint32_t ab = sb + buf * 32768;
        const uint32_t bb = sb + 65536 + buf * 32768;
#pragma unroll
        for (int kk = 0; kk < 4; ++kk) {
            uint32_t ahi[2][4], alo[2][4];
#pragma unroll
            for (int mt = 0; mt < 2; ++mt) {
                uint32_t off = (uint32_t)(aRow0 + mt * 16) * 128 +
                               (uint32_t)(((kk * 2 + aKU) ^ aSwX) << 4);
                LDSM4(ahi[mt], ab + off);
                LDSM4(alo[mt], ab + 16384 + off);
            }
            uint32_t bhi[8][2], blo[8][2];
#pragma unroll
            for (int p = 0; p < 4; ++p) {
                uint32_t off = (uint32_t)(bN0 + p * 16) * 128 +
                               (uint32_t)(((kk * 2 + bKU) ^ aSwX) << 4);
                uint32_t r[4];
                LDSM4(r, bb + off);
                bhi[2 * p][0] = r[0]; bhi[2 * p][1] = r[1];
                bhi[2 * p + 1][0] = r[2]; bhi[2 * p + 1][1] = r[3];
                LDSM4(r, bb + 16384 + off);
                blo[2 * p][0] = r[0]; blo[2 * p][1] = r[1];
                blo[2 * p + 1][0] = r[2]; blo[2 * p + 1][1] = r[3];
            }
#pragma unroll
            for (int mt = 0; mt < 2; ++mt)
#pragma unroll
                for (int nt = 0; nt < 8; ++nt) MMA(acc[mt][nt], ahi[mt], bhi[nt]);
#pragma unroll
            for (int mt = 0; mt < 2; ++mt)
#pragma unroll
                for (int nt = 0; nt < 8; ++nt) MMA(acc[mt][nt], alo[mt], bhi[nt]);
#pragma unroll
            for (int mt = 0; mt < 2; ++mt)
#pragma unroll
                for (int nt = 0; nt < 8; ++nt) MMA(acc[mt][nt], ahi[mt], blo[nt]);
        }
        __syncthreads();
        buf ^= 1;
    }

    // epilogue: direct fragment -> gmem (fp32)
    const int erow = rowBase + wr * 32 + (lane >> 2);
    const int ecol = colBase + wc * 64 + (lane & 3) * 2;
#pragma unroll
    for (int mt = 0; mt < 2; ++mt) {
        size_t r0 = (size_t)(erow + mt * 16) * 256;
#pragma unroll
        for (int nt = 0; nt < 8; ++nt) {
            *(float2*)(Y + r0 + ecol + nt * 8) =
                make_float2(acc[mt][nt][0], acc[mt][nt][1]);
            *(float2*)(Y + r0 + 8 * 256 + ecol + nt * 8) =
                make_float2(acc[mt][nt][2], acc[mt][nt][3]);
        }
    }
}

// ---------------------------------------------------------------------------
// K3: partial batch sums per (n,f). grid (NF/256, NPART); 512 batches each.
// ---------------------------------------------------------------------------
__global__ void k3_partial(const float* __restrict__ Y) {
    const int nf = blockIdx.x * 256 + threadIdx.x;
    const int p = blockIdx.y;
    const float* yp = Y + (size_t)p * 512 * NF + nf;
    float s = 0.f, s2 = 0.f;
#pragma unroll 8
    for (int i = 0; i < 512; ++i) {
        float v = yp[(size_t)i * NF];
        s += v;
        s2 = fmaf(v, v, s2);
    }
    g_psum[p * NF + nf] = s;
    g_psumsq[p * NF + nf] = s2;
}

__global__ void k3b_scaleshift(const float* __restrict__ gamma,
                               const float* __restrict__ beta) {
    const int nf = blockIdx.x * 256 + threadIdx.x;
    float s = 0.f, s2 = 0.f;
#pragma unroll
    for (int p = 0; p < NPART; ++p) {
        s += g_psum[p * NF + nf];
        s2 += g_psumsq[p * NF + nf];
    }
    const float inv = 1.f / (float)B_;
    float mean = s * inv;
    float var = fmaxf(s2 * inv - mean * mean, 0.f);
    int n = nf >> 8;
    int blk = n / 10;
    float g = gamma[blk * NF + nf];
    float sc = g * rsqrtf(var + 1e-5f);
    float bsum = beta[nf] + beta[NF + nf] + beta[2 * NF + nf] + beta[3 * NF + nf];
    g_scale[nf] = sc;
    g_shift[nf] = fmaf(-mean, sc, bsum);
}

__global__ void k4_normalize(float* __restrict__ Y) {
    const size_t gid = (size_t)blockIdx.x * blockDim.x + threadIdx.x;
    const int nf4 = (int)(gid % (NF / 4));
    float4 y = ((const float4*)Y)[gid];
    float4 sc = ((const float4*)g_scale)[nf4];
    float4 sh = ((const float4*)g_shift)[nf4];
    y.x = fmaf(y.x, sc.x, sh.x);
    y.y = fmaf(y.y, sc.y, sh.y);
    y.z = fmaf(y.z, sc.z, sh.z);
    y.w = fmaf(y.w, sc.w, sh.w);
    ((float4*)Y)[gid] = y;
}

// ---------------------------------------------------------------------------
extern "C" void kernel_launch(void* const* d_in, const int* in_sizes, int n_in,
                              void* d_out, int out_size) {
    const float* input = (const float*)d_in[0];
    const float* adj   = (const float*)d_in[1];
    const float* W     = (const float*)d_in[2];
    const float* gamma = (const float*)d_in[3];
    const float* beta  = (const float*)d_in[4];
    float* out = (float*)d_out;

    static bool attr_set = false;
    if (!attr_set) {
        cudaFuncSetAttribute(k2_mma, cudaFuncAttributeMaxDynamicSharedMemorySize, SMEM_K2);
        attr_set = true;
    }

    k0_wprep<<<256, 256>>>(W);
    k1_blockdiag<<<dim3(4, B_), 256>>>(input, adj);
    k2_mma<<<5120, 256, SMEM_K2>>>(out);
    k3_partial<<<dim3(NF / 256, NPART), 256>>>(out);
    k3b_scaleshift<<<NF / 256, 256>>>(gamma, beta);
    k4_normalize<<<(TOT / 4) / 256, 256>>>(out);
}